// round 2
// baseline (speedup 1.0000x reference)
#include <cuda_runtime.h>

#define FULLMASK 0xffffffffu

// ---------------------------------------------------------------------------
// Dimensions (fixed by the problem)
// ---------------------------------------------------------------------------
#define NT 32
#define NB 64
#define ND 512
#define NH 512
#define NP 64

// Scratch: precomputed x-part projection and rotation matrices
__device__ float g_xpre[NT * NB * NP];   // [(t*64+b)*64 + p]
__device__ float g_U[128 * 8];           // [((gate*2+circ)*2+depth)*8+qubit] * 8 floats

// ---------------------------------------------------------------------------
// Kernel 0: precompute the 128 single-qubit rotation matrices U = Rx@Rz@Ry
// ---------------------------------------------------------------------------
__global__ void uprep_kernel(const float* __restrict__ fp, const float* __restrict__ ip,
                             const float* __restrict__ gp, const float* __restrict__ op) {
    int idx = threadIdx.x;
    if (idx >= 128) return;
    int q  = idx & 7;
    int d  = (idx >> 3) & 1;
    int gc = (idx >> 4) & 1;
    int gi = idx >> 5;
    const float* P = (gi == 0) ? fp : (gi == 1) ? ip : (gi == 2) ? gp : op;
    const float* p = P + ((gc * 2 + d) * 8 + q) * 3;
    float a = 0.5f * p[0], b = 0.5f * p[1], c = 0.5f * p[2];
    float ca = cosf(a), sa = sinf(a);
    float cb = cosf(b), sb = sinf(b);
    float cc = cosf(c), sc = sinf(c);
    // M = Rz @ Ry
    float m00r =  ca * cb, m00i = -ca * sb;
    float m01r = -sa * cb, m01i =  sa * sb;
    float m10r =  sa * cb, m10i =  sa * sb;
    float m11r =  ca * cb, m11i =  ca * sb;
    // U = Rx @ M,  Rx = [[cc, -i sc], [-i sc, cc]]
    float* o = g_U + idx * 8;
    o[0] =  cc * m00r + sc * m10i;  o[1] =  cc * m00i - sc * m10r;   // U00
    o[2] =  cc * m01r + sc * m11i;  o[3] =  cc * m01i - sc * m11r;   // U01
    o[4] =  sc * m00i + cc * m10r;  o[5] = -sc * m00r + cc * m10i;   // U10
    o[6] =  sc * m01i + cc * m11r;  o[7] = -sc * m01r + cc * m11i;   // U11
}

// ---------------------------------------------------------------------------
// Kernel 1: xpre[(t*64+b)][p] = b_proj[p] + x_{t,b} . W_proj[p, 0:512]
// One block per (t,b) row; 8 warps, each warp handles 8 p-rows.
// ---------------------------------------------------------------------------
__global__ __launch_bounds__(256, 2)
void xpre_kernel(const float* __restrict__ inputs,
                 const float* __restrict__ W_proj,
                 const float* __restrict__ b_proj) {
    int row = blockIdx.x;            // t*64 + b
    __shared__ float xs[ND];
    int tid = threadIdx.x, lane = tid & 31, wid = tid >> 5;
    xs[tid]       = inputs[row * ND + tid];
    xs[tid + 256] = inputs[row * ND + tid + 256];
    __syncthreads();
    #pragma unroll
    for (int pp = 0; pp < 8; pp++) {
        int p = wid * 8 + pp;
        float acc = 0.f;
        #pragma unroll 4
        for (int k = lane; k < ND; k += 32)
            acc = fmaf(xs[k], W_proj[p * 1024 + k], acc);
        #pragma unroll
        for (int off = 16; off; off >>= 1)
            acc += __shfl_xor_sync(FULLMASK, acc, off);
        if (lane == 0) g_xpre[row * NP + p] = acc + b_proj[p];
    }
}

// ---------------------------------------------------------------------------
// One 8-qubit circuit (2 depths of per-qubit U + CNOT ladder), warp-resident.
// State index k = r*32 + lane (r = register 0..7). Bit p of k <-> qubit 7-p.
// Input/output angles in ang[8] (updated in place with <Z_q> expectations).
// ---------------------------------------------------------------------------
__device__ __forceinline__ void run_circuit(const float* __restrict__ U,
                                            float ang[8], int lane) {
    float cq[8], sq[8];
    #pragma unroll
    for (int q = 0; q < 8; q++) __sincosf(0.5f * ang[q], &sq[q], &cq[q]);

    // Product-state prep: amp[k] = (-i)^popcount(k) * prod(bit? sin : cos)
    float ml = 1.f;
    #pragma unroll
    for (int p = 0; p < 5; p++) ml *= (lane >> p & 1) ? sq[7 - p] : cq[7 - p];
    int pl = __popc(lane);
    float sre[8], sim[8];
    #pragma unroll
    for (int r = 0; r < 8; r++) {
        float m = ml;
        #pragma unroll
        for (int j = 0; j < 3; j++) m *= (r >> j & 1) ? sq[2 - j] : cq[2 - j];
        int pop = (pl + __popc(r)) & 3;
        sre[r] = (pop == 0) ? m : ((pop == 2) ? -m : 0.f);
        sim[r] = (pop == 1) ? -m : ((pop == 3) ? m : 0.f);
    }

    #pragma unroll
    for (int d = 0; d < 2; d++) {
        const float4* Ud = reinterpret_cast<const float4*>(U + d * 64);
        // Qubits 0..2: register-pair gates (k bits 7..5)
        #pragma unroll
        for (int w = 0; w < 3; w++) {
            float4 ua = Ud[w * 2], ub = Ud[w * 2 + 1];
            int mask = 4 >> w;
            #pragma unroll
            for (int r = 0; r < 8; r++) {
                if (r & mask) continue;
                int r1 = r | mask;
                float a0r = sre[r], a0i = sim[r], a1r = sre[r1], a1i = sim[r1];
                sre[r]  = ua.x * a0r - ua.y * a0i + ua.z * a1r - ua.w * a1i;
                sim[r]  = ua.x * a0i + ua.y * a0r + ua.z * a1i + ua.w * a1r;
                sre[r1] = ub.x * a0r - ub.y * a0i + ub.z * a1r - ub.w * a1i;
                sim[r1] = ub.x * a0i + ub.y * a0r + ub.z * a1i + ub.w * a1r;
            }
        }
        // Qubits 3..7: lane-bit gates via shfl_xor (k bits 4..0)
        #pragma unroll
        for (int w = 3; w < 8; w++) {
            float4 ua4 = Ud[w * 2], ub4 = Ud[w * 2 + 1];
            int lm = 1 << (7 - w);
            bool hi = (lane & lm) != 0;
            float uar = hi ? ub4.z : ua4.x, uai = hi ? ub4.w : ua4.y;  // self
            float ubr = hi ? ub4.x : ua4.z, ubi = hi ? ub4.y : ua4.w;  // partner
            #pragma unroll
            for (int r = 0; r < 8; r++) {
                float pr = __shfl_xor_sync(FULLMASK, sre[r], lm);
                float pi = __shfl_xor_sync(FULLMASK, sim[r], lm);
                float nr = uar * sre[r] - uai * sim[r] + ubr * pr - ubi * pi;
                float ni = uar * sim[r] + uai * sre[r] + ubr * pi + ubi * pr;
                sre[r] = nr; sim[r] = ni;
            }
        }
        // CNOT ladder c=0..6 collapses to ONE gather: new[k] = old[k ^ ((k>>1)&127)]
        {
            int g = lane ^ (lane >> 1);
            float nr[8], ni[8];
            #pragma unroll
            for (int r = 0; r < 8; r++) {
                int srr = r ^ (r >> 1);
                int sl  = g ^ ((r & 1) << 4);
                nr[r] = __shfl_sync(FULLMASK, sre[srr], sl);
                ni[r] = __shfl_sync(FULLMASK, sim[srr], sl);
            }
            #pragma unroll
            for (int r = 0; r < 8; r++) { sre[r] = nr[r]; sim[r] = ni[r]; }
        }
    }

    // Measure <Z_q> for all 8 qubits
    float pb[8];
    #pragma unroll
    for (int r = 0; r < 8; r++) pb[r] = sre[r] * sre[r] + sim[r] * sim[r];
    float t0 = pb[0] + pb[1] + pb[2] + pb[3] - pb[4] - pb[5] - pb[6] - pb[7]; // qubit0 (reg bit2)
    float t1 = pb[0] + pb[1] - pb[2] - pb[3] + pb[4] + pb[5] - pb[6] - pb[7]; // qubit1 (reg bit1)
    float t2 = pb[0] - pb[1] + pb[2] - pb[3] + pb[4] - pb[5] + pb[6] - pb[7]; // qubit2 (reg bit0)
    float S  = pb[0] + pb[1] + pb[2] + pb[3] + pb[4] + pb[5] + pb[6] + pb[7];
    #pragma unroll
    for (int off = 16; off; off >>= 1) {
        t0 += __shfl_xor_sync(FULLMASK, t0, off);
        t1 += __shfl_xor_sync(FULLMASK, t1, off);
        t2 += __shfl_xor_sync(FULLMASK, t2, off);
    }
    // Folded butterfly: extracts the 5 lane-bit signed sums during S's reduction
    float zl[5];
    #pragma unroll
    for (int i = 0; i < 5; i++) {
        int off = 16 >> i;
        float u  = __shfl_xor_sync(FULLMASK, S, off);
        float dd = (lane & off) ? (u - S) : (S - u);
        S += u;
        #pragma unroll
        for (int o2 = off >> 1; o2; o2 >>= 1)
            dd += __shfl_xor_sync(FULLMASK, dd, o2);
        zl[i] = dd;
    }
    ang[0] = t0; ang[1] = t1; ang[2] = t2;
    ang[3] = zl[0]; ang[4] = zl[1]; ang[5] = zl[2]; ang[6] = zl[3]; ang[7] = zl[4];
}

__device__ __forceinline__ float fast_sigmoid(float x) { return 1.f / (1.f + __expf(-x)); }
__device__ __forceinline__ float fast_tanh(float x)    { return 2.f / (1.f + __expf(-2.f * x)) - 1.f; }

// ---------------------------------------------------------------------------
// Kernel 2: persistent recurrent kernel. One CTA per batch element, 8 warps.
// Warps 0-3 each simulate one gate's quantum circuits; all warps do GEMV/output.
// ---------------------------------------------------------------------------
__global__ __launch_bounds__(256, 1)
void qlstm_main(const float* __restrict__ W_proj,
                const float* __restrict__ W_toq,
                const float* __restrict__ W_q2h,
                float* __restrict__ out) {
    extern __shared__ float sm[];
    float* WhT  = sm;                  // [512][65]  Wh transposed, padded
    float* wq   = WhT  + 512 * 65;     // [512][9]   W_q2h padded
    float* wtoq = wq   + 512 * 9;      // [8][64]
    float* Usm  = wtoq + 512;          // [128][8]
    float* hx   = Usm  + 1024;         // [512]
    float* proj = hx   + 512;          // [64]
    float* part = proj + 64;           // [256]
    float* ybuf = part + 256;          // [4][8]

    int tid = threadIdx.x, lane = tid & 31, wid = tid >> 5;
    int bb = blockIdx.x;

    // One-time loads
    for (int idx = tid; idx < NP * NH; idx += 256) {
        int p = idx >> 9, k = idx & 511;
        WhT[k * 65 + p] = W_proj[p * 1024 + 512 + k];
    }
    for (int idx = tid; idx < NH * 8; idx += 256)
        wq[(idx >> 3) * 9 + (idx & 7)] = W_q2h[idx];
    for (int idx = tid; idx < 512; idx += 256) wtoq[idx] = W_toq[idx];
    for (int idx = tid; idx < 1024; idx += 256) Usm[idx] = g_U[idx];
    for (int idx = tid; idx < 512; idx += 256) hx[idx] = 0.f;
    float cx0 = 0.f, cx1 = 0.f;
    __syncthreads();

    int p = tid & 63, quarter = tid >> 6;

    #pragma unroll 1
    for (int t = 0; t < NT; t++) {
        // --- proj GEMV: hx @ Wh.T (+ precomputed x part) ---
        float a0 = 0.f, a1 = 0.f, a2 = 0.f, a3 = 0.f;
        int base = quarter * 128;
        #pragma unroll
        for (int kk = 0; kk < 128; kk += 4) {
            a0 = fmaf(hx[base + kk    ], WhT[(base + kk    ) * 65 + p], a0);
            a1 = fmaf(hx[base + kk + 1], WhT[(base + kk + 1) * 65 + p], a1);
            a2 = fmaf(hx[base + kk + 2], WhT[(base + kk + 2) * 65 + p], a2);
            a3 = fmaf(hx[base + kk + 3], WhT[(base + kk + 3) * 65 + p], a3);
        }
        part[tid] = (a0 + a1) + (a2 + a3);
        __syncthreads();
        if (tid < 64)
            proj[tid] = g_xpre[(t * NB + bb) * NP + tid]
                      + ((part[tid] + part[tid + 64]) + (part[tid + 128] + part[tid + 192]));
        __syncthreads();

        // --- quantum gates: warp w = gate w (f,i,g,o) ---
        if (wid < 4) {
            // qin = proj @ W_toq.T, computed redundantly per warp
            int q = lane & 7, seg = lane >> 3;
            float acc = 0.f;
            #pragma unroll
            for (int i = 0; i < 16; i++)
                acc = fmaf(proj[seg * 16 + i], wtoq[q * 64 + seg * 16 + i], acc);
            acc += __shfl_xor_sync(FULLMASK, acc, 8);
            acc += __shfl_xor_sync(FULLMASK, acc, 16);
            float ang[8];
            #pragma unroll
            for (int j = 0; j < 8; j++) ang[j] = __shfl_sync(FULLMASK, acc, j);

            #pragma unroll 1
            for (int gc = 0; gc < 2; gc++)
                run_circuit(Usm + (wid * 2 + gc) * 128, ang, lane);

            if (lane == 0) {
                #pragma unroll
                for (int j = 0; j < 8; j++) ybuf[wid * 8 + j] = ang[j];
            }
        }
        __syncthreads();

        // --- output stage: y @ W_q2h.T, activations, LSTM cell update ---
        #pragma unroll
        for (int u = 0; u < 2; u++) {
            int h = tid + u * 256;
            float af = 0.f, aiv = 0.f, agv = 0.f, aov = 0.f;
            #pragma unroll
            for (int j = 0; j < 8; j++) {
                float w = wq[h * 9 + j];
                af  = fmaf(ybuf[j],      w, af);
                aiv = fmaf(ybuf[8 + j],  w, aiv);
                agv = fmaf(ybuf[16 + j], w, agv);
                aov = fmaf(ybuf[24 + j], w, aov);
            }
            float fv = fast_sigmoid(af);
            float iv = fast_sigmoid(aiv);
            float gv = fast_tanh(agv);
            float ov = fast_sigmoid(aov);
            float cprev = u ? cx1 : cx0;
            float cn = fv * cprev + iv * gv;
            if (u) cx1 = cn; else cx0 = cn;
            float hn = ov * fast_tanh(cn);
            hx[h] = hn;
            out[(t * NB + bb) * NH + h] = hn;
        }
        __syncthreads();
    }

    // Final hx, cx
    #pragma unroll
    for (int u = 0; u < 2; u++) {
        int h = tid + u * 256;
        out[NT * NB * NH + bb * NH + h]           = hx[h];
        out[NT * NB * NH + NB * NH + bb * NH + h] = (u ? cx1 : cx0);
    }
}

// ---------------------------------------------------------------------------
extern "C" void kernel_launch(void* const* d_in, const int* in_sizes, int n_in,
                              void* d_out, int out_size) {
    const float* inputs = (const float*)d_in[0];
    const float* W_proj = (const float*)d_in[1];
    const float* b_proj = (const float*)d_in[2];
    const float* W_toq  = (const float*)d_in[3];
    const float* W_q2h  = (const float*)d_in[4];
    const float* fp     = (const float*)d_in[5];
    const float* ip     = (const float*)d_in[6];
    const float* gp     = (const float*)d_in[7];
    const float* op     = (const float*)d_in[8];
    float* out = (float*)d_out;

    uprep_kernel<<<1, 128>>>(fp, ip, gp, op);
    xpre_kernel<<<NT * NB, 256>>>(inputs, W_proj, b_proj);

    const int SMEM_BYTES = (512 * 65 + 512 * 9 + 512 + 1024 + 512 + 64 + 256 + 32) * (int)sizeof(float);
    cudaFuncSetAttribute(qlstm_main, cudaFuncAttributeMaxDynamicSharedMemorySize, SMEM_BYTES);
    qlstm_main<<<NB, 256, SMEM_BYTES>>>(W_proj, W_toq, W_q2h, out);
}

// round 3
// speedup vs baseline: 1.2599x; 1.2599x over previous
#include <cuda_runtime.h>

#define FULLMASK 0xffffffffu

#define NT 32
#define NB 64
#define ND 512
#define NH 512
#define NP 64

__device__ float g_xpre[NT * NB * NP];   // [(t*64+b)*64 + p]

// ---------------------------------------------------------------------------
// f32x2 packed helpers (FFMA2 path — only reachable via PTX fma.rn.f32x2)
// ---------------------------------------------------------------------------
__device__ __forceinline__ float2 mk2(float a, float b) { float2 r; r.x = a; r.y = b; return r; }

__device__ __forceinline__ float2 f2fma(float2 a, float2 b, float2 c) {
    float2 d;
    asm("fma.rn.f32x2 %0, %1, %2, %3;"
        : "=l"(reinterpret_cast<unsigned long long&>(d))
        : "l"(reinterpret_cast<unsigned long long&>(a)),
          "l"(reinterpret_cast<unsigned long long&>(b)),
          "l"(reinterpret_cast<unsigned long long&>(c)));
    return d;
}
__device__ __forceinline__ float2 f2mul(float2 a, float2 b) {
    float2 d;
    asm("mul.rn.f32x2 %0, %1, %2;"
        : "=l"(reinterpret_cast<unsigned long long&>(d))
        : "l"(reinterpret_cast<unsigned long long&>(a)),
          "l"(reinterpret_cast<unsigned long long&>(b)));
    return d;
}

// ---------------------------------------------------------------------------
// Kernel 1: xpre[(t*64+b)][p] = b_proj[p] + x_row . W_proj[p, 0:512]
// 128 blocks x 16 rows; weights register-cached per thread.
// ---------------------------------------------------------------------------
__global__ __launch_bounds__(256, 1)
void xpre_kernel(const float* __restrict__ inputs,
                 const float* __restrict__ W_proj,
                 const float* __restrict__ b_proj) {
    __shared__ __align__(16) float xs[16 * ND];
    __shared__ float part[256];
    __shared__ float bsm[64];
    int tid = threadIdx.x;
    int p = tid & 63, quarter = tid >> 6;
    int blk = blockIdx.x;

    float4 wv[32];
    const float4* wp = reinterpret_cast<const float4*>(W_proj + p * 1024 + quarter * 128);
    #pragma unroll
    for (int i = 0; i < 32; i++) wv[i] = wp[i];
    if (tid < 64) bsm[tid] = b_proj[tid];
    for (int i = tid; i < 16 * ND; i += 256) xs[i] = inputs[blk * (16 * ND) + i];
    __syncthreads();

    #pragma unroll 1
    for (int row = 0; row < 16; row++) {
        const float4* hp = reinterpret_cast<const float4*>(xs + row * ND + quarter * 128);
        float2 acc = mk2(0.f, 0.f);
        #pragma unroll
        for (int i = 0; i < 32; i++) {
            float4 hv = hp[i];
            acc = f2fma(mk2(hv.x, hv.y), mk2(wv[i].x, wv[i].y), acc);
            acc = f2fma(mk2(hv.z, hv.w), mk2(wv[i].z, wv[i].w), acc);
        }
        part[tid] = acc.x + acc.y;
        __syncthreads();
        if (tid < 64)
            g_xpre[(blk * 16 + row) * NP + tid] =
                bsm[tid] + ((part[tid] + part[tid + 64]) + (part[tid + 128] + part[tid + 192]));
        __syncthreads();
    }
}

// ---------------------------------------------------------------------------
// One 8-qubit circuit, warp-resident, f32x2-packed state.
// Packing: reg j holds amps (k = j*32+lane, k = (j+4)*32+lane) as (x, y).
// k bit7 = packing half, bits 6:5 = j bits 1:0, bits 4:0 = lane.
// ---------------------------------------------------------------------------
__device__ __forceinline__ void run_circuit(const float* __restrict__ U,
                                            float ang[8], int lane) {
    float cq[8], sq[8];
    #pragma unroll
    for (int q = 0; q < 8; q++) __sincosf(0.5f * ang[q], &sq[q], &cq[q]);

    // Product-state prep: amp[k] = (-i)^popcount(k) * prod(bit? sin : cos)
    float ml = 1.f;
    #pragma unroll
    for (int p = 0; p < 5; p++) ml *= (lane >> p & 1) ? sq[7 - p] : cq[7 - p];
    int pl = __popc(lane);
    float sre[8], sim[8];
    #pragma unroll
    for (int r = 0; r < 8; r++) {
        float m = ml;
        #pragma unroll
        for (int j = 0; j < 3; j++) m *= (r >> j & 1) ? sq[2 - j] : cq[2 - j];
        int pop = (pl + __popc(r)) & 3;
        sre[r] = (pop == 0) ? m : ((pop == 2) ? -m : 0.f);
        sim[r] = (pop == 1) ? -m : ((pop == 3) ? m : 0.f);
    }
    float2 RE[4], IM[4];
    #pragma unroll
    for (int j = 0; j < 4; j++) { RE[j] = mk2(sre[j], sre[j + 4]); IM[j] = mk2(sim[j], sim[j + 4]); }

    #pragma unroll
    for (int d = 0; d < 2; d++) {
        const float4* Ud = reinterpret_cast<const float4*>(U + d * 64);
        // ---- qubit 0 (k bit7 = packing dim): half-swap gate ----
        {
            float4 ua = Ud[0], ub = Ud[1];
            float2 c0r  = mk2(ua.x,  ub.z);   // (u00r, u11r)
            float2 c0i  = mk2(ua.y,  ub.w);   // (u00i, u11i)
            float2 c0in = mk2(-ua.y, -ub.w);
            float2 c1r  = mk2(ua.z,  ub.x);   // (u01r, u10r)
            float2 c1i  = mk2(ua.w,  ub.y);
            float2 c1in = mk2(-ua.w, -ub.y);
            #pragma unroll
            for (int j = 0; j < 4; j++) {
                float2 Ro = RE[j], Io = IM[j];
                float2 Rs = mk2(Ro.y, Ro.x), Is = mk2(Io.y, Io.x);
                RE[j] = f2fma(Is, c1in, f2fma(Rs, c1r, f2fma(Io, c0in, f2mul(Ro, c0r))));
                IM[j] = f2fma(Rs, c1i,  f2fma(Is, c1r, f2fma(Ro, c0i,  f2mul(Io, c0r))));
            }
        }
        // ---- qubits 1,2 (k bits 6,5 = reg-index bits): packed pair gates ----
        #pragma unroll
        for (int w = 1; w < 3; w++) {
            float4 ua = Ud[w * 2], ub = Ud[w * 2 + 1];
            float2 s00r = mk2(ua.x, ua.x), s00i = mk2(ua.y, ua.y), s00in = mk2(-ua.y, -ua.y);
            float2 s01r = mk2(ua.z, ua.z), s01i = mk2(ua.w, ua.w), s01in = mk2(-ua.w, -ua.w);
            float2 s10r = mk2(ub.x, ub.x), s10i = mk2(ub.y, ub.y), s10in = mk2(-ub.y, -ub.y);
            float2 s11r = mk2(ub.z, ub.z), s11i = mk2(ub.w, ub.w), s11in = mk2(-ub.w, -ub.w);
            int m = (w == 1) ? 2 : 1;
            #pragma unroll
            for (int j = 0; j < 4; j++) {
                if (j & m) continue;
                int j1 = j | m;
                float2 a0R = RE[j], a0I = IM[j], a1R = RE[j1], a1I = IM[j1];
                RE[j]  = f2fma(a1I, s01in, f2fma(a1R, s01r, f2fma(a0I, s00in, f2mul(a0R, s00r))));
                IM[j]  = f2fma(a1R, s01i,  f2fma(a1I, s01r, f2fma(a0R, s00i,  f2mul(a0I, s00r))));
                RE[j1] = f2fma(a1I, s11in, f2fma(a1R, s11r, f2fma(a0I, s10in, f2mul(a0R, s10r))));
                IM[j1] = f2fma(a1R, s11i,  f2fma(a1I, s11r, f2fma(a0R, s10i,  f2mul(a0I, s10r))));
            }
        }
        // ---- qubits 3..7 (lane bits 4..0): shfl gates ----
        #pragma unroll
        for (int w = 3; w < 8; w++) {
            float4 ua4 = Ud[w * 2], ub4 = Ud[w * 2 + 1];
            int lm = 1 << (7 - w);
            bool hi = (lane & lm) != 0;
            float uar = hi ? ub4.z : ua4.x, uai = hi ? ub4.w : ua4.y;  // self
            float ubr = hi ? ub4.x : ua4.z, ubi = hi ? ub4.y : ua4.w;  // partner
            float2 sar = mk2(uar, uar), sai = mk2(uai, uai), sain = mk2(-uai, -uai);
            float2 sbr = mk2(ubr, ubr), sbi = mk2(ubi, ubi), sbin = mk2(-ubi, -ubi);
            #pragma unroll
            for (int j = 0; j < 4; j++) {
                float2 P, Q;
                P.x = __shfl_xor_sync(FULLMASK, RE[j].x, lm);
                P.y = __shfl_xor_sync(FULLMASK, RE[j].y, lm);
                Q.x = __shfl_xor_sync(FULLMASK, IM[j].x, lm);
                Q.y = __shfl_xor_sync(FULLMASK, IM[j].y, lm);
                float2 Ro = RE[j], Io = IM[j];
                RE[j] = f2fma(Q, sbin, f2fma(P, sbr, f2fma(Io, sain, f2mul(Ro, sar))));
                IM[j] = f2fma(P, sbi,  f2fma(Q, sbr, f2fma(Ro, sai,  f2mul(Io, sar))));
            }
        }
        // ---- CNOT ladder == one gather: new[k] = old[k ^ ((k>>1)&127)] ----
        {
            int g0 = lane ^ (lane >> 1);
            float2 nR[4], nI[4];
            #pragma unroll
            for (int j = 0; j < 4; j++) {
                int sl = g0 ^ ((j & 1) << 4);
                int sA = j ^ (j >> 1), sB = sA ^ 2;
                nR[j].x = __shfl_sync(FULLMASK, RE[sA].x, sl);
                nR[j].y = __shfl_sync(FULLMASK, RE[sB].y, sl);
                nI[j].x = __shfl_sync(FULLMASK, IM[sA].x, sl);
                nI[j].y = __shfl_sync(FULLMASK, IM[sB].y, sl);
            }
            #pragma unroll
            for (int j = 0; j < 4; j++) { RE[j] = nR[j]; IM[j] = nI[j]; }
        }
    }

    // ---- Measure <Z_q> ----
    float pb[8];
    #pragma unroll
    for (int j = 0; j < 4; j++) {
        float2 p2 = f2fma(IM[j], IM[j], f2mul(RE[j], RE[j]));
        pb[j] = p2.x; pb[j + 4] = p2.y;
    }
    float t0 = pb[0] + pb[1] + pb[2] + pb[3] - pb[4] - pb[5] - pb[6] - pb[7];
    float t1 = pb[0] + pb[1] - pb[2] - pb[3] + pb[4] + pb[5] - pb[6] - pb[7];
    float t2 = pb[0] - pb[1] + pb[2] - pb[3] + pb[4] - pb[5] + pb[6] - pb[7];
    float S  = pb[0] + pb[1] + pb[2] + pb[3] + pb[4] + pb[5] + pb[6] + pb[7];
    #pragma unroll
    for (int off = 16; off; off >>= 1) {
        t0 += __shfl_xor_sync(FULLMASK, t0, off);
        t1 += __shfl_xor_sync(FULLMASK, t1, off);
        t2 += __shfl_xor_sync(FULLMASK, t2, off);
    }
    float zl[5];
    #pragma unroll
    for (int i = 0; i < 5; i++) {
        int off = 16 >> i;
        float u  = __shfl_xor_sync(FULLMASK, S, off);
        float dd = (lane & off) ? (u - S) : (S - u);
        S += u;
        #pragma unroll
        for (int o2 = off >> 1; o2; o2 >>= 1)
            dd += __shfl_xor_sync(FULLMASK, dd, o2);
        zl[i] = dd;
    }
    ang[0] = t0; ang[1] = t1; ang[2] = t2;
    ang[3] = zl[0]; ang[4] = zl[1]; ang[5] = zl[2]; ang[6] = zl[3]; ang[7] = zl[4];
}

__device__ __forceinline__ float fast_sigmoid(float x) { return 1.f / (1.f + __expf(-x)); }
__device__ __forceinline__ float fast_tanh(float x)    { return 2.f / (1.f + __expf(-2.f * x)) - 1.f; }

// ---------------------------------------------------------------------------
// Kernel 2: persistent recurrent kernel. One CTA per batch element, 8 warps.
// Wh weights register-cached (128 regs/thread). Warps 0-3 run the circuits.
// ---------------------------------------------------------------------------
__global__ __launch_bounds__(256, 1)
void qlstm_main(const float* __restrict__ W_proj,
                const float* __restrict__ W_toq,
                const float* __restrict__ W_q2h,
                const float* __restrict__ fpar, const float* __restrict__ ipar,
                const float* __restrict__ gpar, const float* __restrict__ opar,
                float* __restrict__ out) {
    __shared__ float wq[NH * 9];           // W_q2h padded
    __shared__ float wtoq[8 * 64];
    __shared__ float Usm[128 * 8];
    __shared__ __align__(16) float hx[NH];
    __shared__ float proj[64];
    __shared__ float part[256];
    __shared__ float ybuf[32];

    int tid = threadIdx.x, lane = tid & 31, wid = tid >> 5;
    int bb = blockIdx.x;
    int p = tid & 63, quarter = tid >> 6;

    // Register-cache this thread's Wh slice: rows p, cols [quarter*128, +128)
    float4 wv[32];
    {
        const float4* wp = reinterpret_cast<const float4*>(W_proj + p * 1024 + 512 + quarter * 128);
        #pragma unroll
        for (int i = 0; i < 32; i++) wv[i] = wp[i];
    }

    // One-time smem loads
    for (int idx = tid; idx < NH * 8; idx += 256)
        wq[(idx >> 3) * 9 + (idx & 7)] = W_q2h[idx];
    for (int idx = tid; idx < 512; idx += 256) wtoq[idx] = W_toq[idx];
    for (int idx = tid; idx < 512; idx += 256) hx[idx] = 0.f;

    // In-kernel U prep: thread idx<128 computes one U = Rx@Rz@Ry
    if (tid < 128) {
        int q = tid & 7, d = (tid >> 3) & 1, gc = (tid >> 4) & 1, gi = tid >> 5;
        const float* P = (gi == 0) ? fpar : (gi == 1) ? ipar : (gi == 2) ? gpar : opar;
        const float* pp = P + ((gc * 2 + d) * 8 + q) * 3;
        float a = 0.5f * pp[0], b = 0.5f * pp[1], c = 0.5f * pp[2];
        float ca = cosf(a), sa = sinf(a);
        float cb = cosf(b), sb = sinf(b);
        float cc = cosf(c), sc = sinf(c);
        float m00r =  ca * cb, m00i = -ca * sb;
        float m01r = -sa * cb, m01i =  sa * sb;
        float m10r =  sa * cb, m10i =  sa * sb;
        float m11r =  ca * cb, m11i =  ca * sb;
        float* o = Usm + tid * 8;
        o[0] =  cc * m00r + sc * m10i;  o[1] =  cc * m00i - sc * m10r;
        o[2] =  cc * m01r + sc * m11i;  o[3] =  cc * m01i - sc * m11r;
        o[4] =  sc * m00i + cc * m10r;  o[5] = -sc * m00r + cc * m10i;
        o[6] =  sc * m01i + cc * m11r;  o[7] = -sc * m01r + cc * m11i;
    }
    float cx0 = 0.f, cx1 = 0.f;
    __syncthreads();

    #pragma unroll 1
    for (int t = 0; t < NT; t++) {
        // --- proj GEMV: hx @ Wh.T (register weights) + precomputed x part ---
        {
            const float4* hp = reinterpret_cast<const float4*>(hx + quarter * 128);
            float2 acc = mk2(0.f, 0.f);
            #pragma unroll
            for (int i = 0; i < 32; i++) {
                float4 hv = hp[i];
                acc = f2fma(mk2(hv.x, hv.y), mk2(wv[i].x, wv[i].y), acc);
                acc = f2fma(mk2(hv.z, hv.w), mk2(wv[i].z, wv[i].w), acc);
            }
            part[tid] = acc.x + acc.y;
        }
        __syncthreads();
        if (tid < 64)
            proj[tid] = g_xpre[(t * NB + bb) * NP + tid]
                      + ((part[tid] + part[tid + 64]) + (part[tid + 128] + part[tid + 192]));
        __syncthreads();

        // --- quantum gates: warp w = gate w (f,i,g,o) ---
        if (wid < 4) {
            int q = lane & 7, seg = lane >> 3;
            float acc = 0.f;
            #pragma unroll
            for (int i = 0; i < 16; i++)
                acc = fmaf(proj[seg * 16 + i], wtoq[q * 64 + seg * 16 + i], acc);
            acc += __shfl_xor_sync(FULLMASK, acc, 8);
            acc += __shfl_xor_sync(FULLMASK, acc, 16);
            float ang[8];
            #pragma unroll
            for (int j = 0; j < 8; j++) ang[j] = __shfl_sync(FULLMASK, acc, j);

            #pragma unroll 1
            for (int gc = 0; gc < 2; gc++)
                run_circuit(Usm + (wid * 2 + gc) * 128, ang, lane);

            if (lane == 0) {
                #pragma unroll
                for (int j = 0; j < 8; j++) ybuf[wid * 8 + j] = ang[j];
            }
        }
        __syncthreads();

        // --- output stage: y @ W_q2h.T, activations, LSTM cell update ---
        #pragma unroll
        for (int u = 0; u < 2; u++) {
            int h = tid + u * 256;
            float af = 0.f, aiv = 0.f, agv = 0.f, aov = 0.f;
            #pragma unroll
            for (int j = 0; j < 8; j++) {
                float w = wq[h * 9 + j];
                af  = fmaf(ybuf[j],      w, af);
                aiv = fmaf(ybuf[8 + j],  w, aiv);
                agv = fmaf(ybuf[16 + j], w, agv);
                aov = fmaf(ybuf[24 + j], w, aov);
            }
            float fv = fast_sigmoid(af);
            float iv = fast_sigmoid(aiv);
            float gv = fast_tanh(agv);
            float ov = fast_sigmoid(aov);
            float cprev = u ? cx1 : cx0;
            float cn = fv * cprev + iv * gv;
            if (u) cx1 = cn; else cx0 = cn;
            float hn = ov * fast_tanh(cn);
            hx[h] = hn;
            out[(t * NB + bb) * NH + h] = hn;
        }
        __syncthreads();
    }

    #pragma unroll
    for (int u = 0; u < 2; u++) {
        int h = tid + u * 256;
        out[NT * NB * NH + bb * NH + h]           = hx[h];
        out[NT * NB * NH + NB * NH + bb * NH + h] = (u ? cx1 : cx0);
    }
}

// ---------------------------------------------------------------------------
extern "C" void kernel_launch(void* const* d_in, const int* in_sizes, int n_in,
                              void* d_out, int out_size) {
    const float* inputs = (const float*)d_in[0];
    const float* W_proj = (const float*)d_in[1];
    const float* b_proj = (const float*)d_in[2];
    const float* W_toq  = (const float*)d_in[3];
    const float* W_q2h  = (const float*)d_in[4];
    const float* fp     = (const float*)d_in[5];
    const float* ip     = (const float*)d_in[6];
    const float* gp     = (const float*)d_in[7];
    const float* op     = (const float*)d_in[8];
    float* out = (float*)d_out;

    xpre_kernel<<<128, 256>>>(inputs, W_proj, b_proj);
    qlstm_main<<<NB, 256>>>(W_proj, W_toq, W_q2h, fp, ip, gp, op, out);
}